// round 2
// baseline (speedup 1.0000x reference)
#include <cuda_runtime.h>

// out[t, 0, :] = inputs[t, :]
// out[t, l, :] = memory[l, :]  for l in [1, 64)
// T=2048, L=64, D=1024 (fp32). Pure write-bandwidth kernel.

constexpr int T = 2048;
constexpr int L = 64;
constexpr int D = 1024;
constexpr int D4 = D / 4;          // 256 float4 per (t,l) row
constexpr int ROW4 = L * D4;       // float4 per t

__global__ __launch_bounds__(256, 8)
void sliding_window_memory_kernel(const float4* __restrict__ inp,
                                  const float4* __restrict__ mem,
                                  float4* __restrict__ out) {
    const int t   = blockIdx.x;
    const int tid = threadIdx.x;            // 0..255 == float4 column

    float4* orow = out + (size_t)t * ROW4;

    // slot 0: inputs[t]
    orow[tid] = inp[t * D4 + tid];

    // slots 1..63: broadcast memory rows (L1/L2 resident after first touch)
    #pragma unroll 7
    for (int l = 1; l < L; ++l) {
        orow[l * D4 + tid] = mem[l * D4 + tid];
    }
}

extern "C" void kernel_launch(void* const* d_in, const int* in_sizes, int n_in,
                              void* d_out, int out_size) {
    const float4* inp = (const float4*)d_in[0];   // [T, D] fp32
    const float4* mem = (const float4*)d_in[1];   // [L, D] fp32
    float4* out = (float4*)d_out;                 // [T, L, D] fp32

    sliding_window_memory_kernel<<<T, 256>>>(inp, mem, out);
}

// round 3
// speedup vs baseline: 1.0478x; 1.0478x over previous
#include <cuda_runtime.h>

// out[t, 0, :] = inputs[t, :]
// out[t, l, :] = memory[l, :]  for l in [1, 64)
// T=2048, L=64, D=1024 (fp32). 512 MB of writes -> pure DRAM-write kernel.
//
// Transposed schedule: block (x=t-chunk, y=l). For l>=1 the row is invariant
// in t, so each thread holds its float4 of memory[l] in a REGISTER and issues
// 64 pure streaming stores (no load traffic in steady state). l==0 blocks
// copy inputs[t] per t.

constexpr int T  = 2048;
constexpr int L  = 64;
constexpr int D  = 1024;
constexpr int D4 = D / 4;            // 256 float4 per row -> 256 threads
constexpr int ROW4 = L * D4;         // float4 per t
constexpr int TT = 64;               // t-values per block
constexpr int TBLK = T / TT;         // 32 blocks along t

__global__ __launch_bounds__(256, 8)
void sliding_window_memory_kernel(const float4* __restrict__ inp,
                                  const float4* __restrict__ mem,
                                  float4* __restrict__ out) {
    const int l   = blockIdx.y;          // 0..63
    const int t0  = blockIdx.x * TT;     // base t for this block
    const int tid = threadIdx.x;         // float4 column 0..255

    if (l == 0) {
        // slot 0 depends on t: copy inputs[t0..t0+TT)
        const float4* ip = inp + (size_t)t0 * D4 + tid;
        float4*       op = out + (size_t)t0 * ROW4 + tid;
        #pragma unroll 8
        for (int i = 0; i < TT; ++i) {
            __stcs(op, __ldg(ip));
            ip += D4;
            op += ROW4;
        }
    } else {
        // slots 1..63: row is t-invariant -> register-held, pure store stream
        const float4 v = __ldg(mem + (size_t)l * D4 + tid);
        float4* op = out + (size_t)t0 * ROW4 + (size_t)l * D4 + tid;
        #pragma unroll 16
        for (int i = 0; i < TT; ++i) {
            __stcs(op, v);
            op += ROW4;
        }
    }
}

extern "C" void kernel_launch(void* const* d_in, const int* in_sizes, int n_in,
                              void* d_out, int out_size) {
    const float4* inp = (const float4*)d_in[0];   // [T, D] fp32
    const float4* mem = (const float4*)d_in[1];   // [L, D] fp32
    float4* out = (float4*)d_out;                 // [T, L, D] fp32

    dim3 grid(TBLK, L);
    sliding_window_memory_kernel<<<grid, 256>>>(inp, mem, out);
}

// round 4
// speedup vs baseline: 1.1321x; 1.0804x over previous
#include <cuda_runtime.h>

// out[t, 0, :] = inputs[t, :]
// out[t, l, :] = memory[l, :]  for l in [1, 64)
// T=2048, L=64, D=1024 (fp32). 512 MB pure-write kernel.
//
// TLB-aware schedule: output spans 512MB = 256 x 2MB pages but the TLB holds
// only 128 entries. Grid is (x=l, y=t-chunk) with small TT=16 chunks so the
// ~1184 concurrently-resident blocks touch only ~74MB (~37 pages) at a time.
// l>=1 rows are t-invariant: held in a register, emitted as a pure streaming
// store sequence (no loads in steady state).

constexpr int T  = 2048;
constexpr int L  = 64;
constexpr int D  = 1024;
constexpr int D4 = D / 4;            // 256 float4 per row -> 256 threads
constexpr int ROW4 = L * D4;         // float4 per t (16K float4 = 256KB)
constexpr int TT = 16;               // t-values per block (4MB address span)
constexpr int CH = T / TT;           // 128 chunks along t

__global__ __launch_bounds__(256, 8)
void sliding_window_memory_kernel(const float4* __restrict__ inp,
                                  const float4* __restrict__ mem,
                                  float4* __restrict__ out) {
    const int l   = blockIdx.x;          // 0..63  (fast dim: concurrent blocks
    const int t0  = blockIdx.y * TT;     //         share the same 4MB chunk)
    const int tid = threadIdx.x;         // float4 column 0..255

    if (l == 0) {
        // slot 0 depends on t: copy inputs[t0..t0+TT)
        const float4* ip = inp + (size_t)t0 * D4 + tid;
        float4*       op = out + (size_t)t0 * ROW4 + tid;
        #pragma unroll
        for (int i = 0; i < TT; ++i) {
            __stcs(op, __ldg(ip));
            ip += D4;
            op += ROW4;
        }
    } else {
        // slots 1..63: t-invariant row -> register-held, pure store stream
        const float4 v = __ldg(mem + (size_t)l * D4 + tid);
        float4* op = out + (size_t)t0 * ROW4 + (size_t)l * D4 + tid;
        #pragma unroll
        for (int i = 0; i < TT; ++i) {
            __stcs(op, v);
            op += ROW4;
        }
    }
}

extern "C" void kernel_launch(void* const* d_in, const int* in_sizes, int n_in,
                              void* d_out, int out_size) {
    const float4* inp = (const float4*)d_in[0];   // [T, D] fp32
    const float4* mem = (const float4*)d_in[1];   // [L, D] fp32
    float4* out = (float4*)d_out;                 // [T, L, D] fp32

    dim3 grid(L, CH);
    sliding_window_memory_kernel<<<grid, 256>>>(inp, mem, out);
}